// round 2
// baseline (speedup 1.0000x reference)
#include <cuda_runtime.h>
#include <math_constants.h>

// ---------------- problem constants ----------------
#define BATCH 4
#define NTOK 4096            // 64*64
#define CIN 256
#define ADIM 128
#define MTOT (BATCH*NTOK)    // 16384
#define NEG_SLOPE 0.2f

// ---------------- scratch (no allocations allowed) ----------------
__device__ float g_Q[MTOT * ADIM];
__device__ float g_K[MTOT * ADIM];
__device__ float g_V[MTOT * ADIM];
__device__ float g_O[MTOT * ADIM];

// ---------------- f32x2 packed helpers ----------------
typedef unsigned long long ull;

__device__ __forceinline__ ull pack2(float lo, float hi) {
    ull r; asm("mov.b64 %0, {%1,%2};" : "=l"(r) : "f"(lo), "f"(hi)); return r;
}
__device__ __forceinline__ void unpack2(ull v, float &lo, float &hi) {
    asm("mov.b64 {%0,%1}, %2;" : "=f"(lo), "=f"(hi) : "l"(v));
}
__device__ __forceinline__ ull ffma2(ull a, ull b, ull c) {
    ull d; asm("fma.rn.f32x2 %0, %1, %2, %3;" : "=l"(d) : "l"(a), "l"(b), "l"(c)); return d;
}
__device__ __forceinline__ ull fmul2(ull a, ull b) {
    ull d; asm("mul.rn.f32x2 %0, %1, %2;" : "=l"(d) : "l"(a), "l"(b)); return d;
}

__device__ __forceinline__ float lrelu(float x) {
    return x >= 0.0f ? x : NEG_SLOPE * x;
}

// =====================================================================
// Kernel 1: QKV projection.  Out[m, a] = lrelu(sum_c X[m,c] * W[c,a])
// M=16384, K=256, N=128.  BM=128, BK=64, 256 threads, 8x8 microtile
// (packed as 8 rows x 4 f32x2 column-pairs).
// grid = (128, 1, 3)  z selects Wq/Wk/Wv -> g_Q/g_K/g_V
// smem: Xs[128][66] + Ws[64][128]
// =====================================================================
#define QKV_SMEM ((128*66 + 64*128) * 4)

__global__ __launch_bounds__(256)
void qkv_kernel(const float* __restrict__ X,
                const float* __restrict__ Wq,
                const float* __restrict__ Wk,
                const float* __restrict__ Wv) {
    extern __shared__ float sm[];
    float* Xs = sm;                 // [128][66]
    float* Ws = sm + 128 * 66;      // [64][128]

    const float* Wsel = (blockIdx.z == 0) ? Wq : (blockIdx.z == 1) ? Wk : Wv;
    float* Out = (blockIdx.z == 0) ? g_Q : (blockIdx.z == 1) ? g_K : g_V;

    const int tid = threadIdx.x;
    const int tx = tid & 15;        // 16 col-groups (8 cols each)
    const int ty = tid >> 4;        // 16 row-groups (8 rows each)
    const int row0 = blockIdx.x * 128;

    ull acc[8][4];
    #pragma unroll
    for (int i = 0; i < 8; i++)
        #pragma unroll
        for (int j = 0; j < 4; j++) acc[i][j] = 0ull;

    for (int kc = 0; kc < CIN; kc += 64) {
        // load X tile 128x64 (float4 gmem, 2x float2 smem store: stride 66)
        #pragma unroll
        for (int it = 0; it < 8; it++) {
            int i = tid + it * 256;          // 2048 float4 total
            int r = i >> 4;
            int c = (i & 15) << 2;
            float4 v = *(const float4*)&X[(size_t)(row0 + r) * CIN + kc + c];
            float* d = &Xs[r * 66 + c];
            *(float2*)d = make_float2(v.x, v.y);
            *(float2*)(d + 2) = make_float2(v.z, v.w);
        }
        // load W tile 64x128
        #pragma unroll
        for (int it = 0; it < 8; it++) {
            int i = tid + it * 256;          // 2048 float4 total
            int r = i >> 5;
            int c = (i & 31) << 2;
            *(float4*)&Ws[r * 128 + c] =
                *(const float4*)&Wsel[(size_t)(kc + r) * ADIM + c];
        }
        __syncthreads();

        #pragma unroll 8
        for (int k = 0; k < 64; k++) {
            ull b[4];
            #pragma unroll
            for (int jc = 0; jc < 4; jc++)
                b[jc] = *(const ull*)&Ws[k * 128 + tx * 8 + jc * 2];
            #pragma unroll
            for (int i = 0; i < 8; i++) {
                float a = Xs[(ty * 8 + i) * 66 + k];
                ull a2 = pack2(a, a);
                #pragma unroll
                for (int jc = 0; jc < 4; jc++)
                    acc[i][jc] = ffma2(a2, b[jc], acc[i][jc]);
            }
        }
        __syncthreads();
    }

    // epilogue: leaky relu + store
    #pragma unroll
    for (int i = 0; i < 8; i++) {
        int row = row0 + ty * 8 + i;
        #pragma unroll
        for (int jc = 0; jc < 4; jc++) {
            float lo, hi; unpack2(acc[i][jc], lo, hi);
            lo = lrelu(lo); hi = lrelu(hi);
            *(float2*)&Out[(size_t)row * ADIM + tx * 8 + jc * 2] = make_float2(lo, hi);
        }
    }
}

// =====================================================================
// Kernel 2: flash attention, fp32, no scale.
//   per block: 64 query rows of one batch, loop over 64 KV tiles of 64.
// grid = (64, 4), 256 threads.
// smem: Qs[64][130] | Ks[64][130] (reused as Ps[64][65]) | Vs[64][128]
// Thread map S:  rows ty*4+i (i<4), cols tx*4+j (j<4)
// Thread map O:  rows ty*4+i (i<4), cols tx*8+2*jc (jc<4, f32x2 pairs)
// =====================================================================
#define ATTN_SMEM ((64*130 + 64*130 + 64*128) * 4)

__global__ __launch_bounds__(256)
void attn_kernel() {
    extern __shared__ float sm[];
    float* Qs = sm;                   // [64][130]
    float* Ks = sm + 64 * 130;        // [64][130]
    float* Vs = sm + 2 * 64 * 130;    // [64][128]
    float* Ps = Ks;                   // overlay: P written after S consumed

    const int b = blockIdx.y;
    const int q0 = blockIdx.x * 64;
    const int tid = threadIdx.x;
    const int tx = tid & 15;
    const int ty = tid >> 4;

    const float* Qg = g_Q + (size_t)(b * NTOK + q0) * ADIM;

    // load Q tile 64x128 -> stride 130
    #pragma unroll
    for (int it = 0; it < 16; it++) {
        int i = tid + it * 256;       // 4096 float2 total
        int r = i >> 6;
        int c = (i & 63) << 1;
        *(float2*)&Qs[r * 130 + c] = *(const float2*)&Qg[r * ADIM + c];
    }

    float m[4], l[4];
    ull oacc[4][4];
    #pragma unroll
    for (int i = 0; i < 4; i++) {
        m[i] = -CUDART_INF_F; l[i] = 0.0f;
        #pragma unroll
        for (int jc = 0; jc < 4; jc++) oacc[i][jc] = 0ull;
    }

    for (int t = 0; t < 64; t++) {
        __syncthreads();   // previous PV done reading Vs / Ps(=Ks)
        const float* Kg = g_K + (size_t)(b * NTOK + t * 64) * ADIM;
        const float* Vg = g_V + (size_t)(b * NTOK + t * 64) * ADIM;
        #pragma unroll
        for (int it = 0; it < 16; it++) {
            int i = tid + it * 256;
            int r = i >> 6;
            int c = (i & 63) << 1;
            *(float2*)&Ks[r * 130 + c] = *(const float2*)&Kg[r * ADIM + c];
            *(float2*)&Vs[r * 128 + c] = *(const float2*)&Vg[r * ADIM + c];
        }
        __syncthreads();

        // ---- S = Q K^T (pack over k) ----
        ull sa[4][4];
        #pragma unroll
        for (int i = 0; i < 4; i++)
            #pragma unroll
            for (int j = 0; j < 4; j++) sa[i][j] = 0ull;

        const float* qbase = &Qs[(ty * 4) * 130];
        const float* kbase = &Ks[(tx * 4) * 130];
        #pragma unroll 8
        for (int kp = 0; kp < 64; kp++) {
            ull qv[4], kv[4];
            #pragma unroll
            for (int i = 0; i < 4; i++)
                qv[i] = *(const ull*)&qbase[i * 130 + kp * 2];
            #pragma unroll
            for (int j = 0; j < 4; j++)
                kv[j] = *(const ull*)&kbase[j * 130 + kp * 2];
            #pragma unroll
            for (int i = 0; i < 4; i++)
                #pragma unroll
                for (int j = 0; j < 4; j++)
                    sa[i][j] = ffma2(qv[i], kv[j], sa[i][j]);
        }
        float s[4][4];
        #pragma unroll
        for (int i = 0; i < 4; i++)
            #pragma unroll
            for (int j = 0; j < 4; j++) {
                float lo, hi; unpack2(sa[i][j], lo, hi);
                s[i][j] = lo + hi;
            }

        __syncthreads();   // all Ks reads done before Ps overlay writes

        // ---- online softmax (row groups: each row lives in 16 lanes) ----
        #pragma unroll
        for (int i = 0; i < 4; i++) {
            float mx = fmaxf(fmaxf(s[i][0], s[i][1]), fmaxf(s[i][2], s[i][3]));
            #pragma unroll
            for (int off = 8; off >= 1; off >>= 1)
                mx = fmaxf(mx, __shfl_xor_sync(0xffffffffu, mx, off));
            float mnew = fmaxf(m[i], mx);
            float sum = 0.0f;
            int prow = (ty * 4 + i) * 65;
            #pragma unroll
            for (int j = 0; j < 4; j++) {
                float p = __expf(s[i][j] - mnew);
                sum += p;
                Ps[prow + tx * 4 + j] = p;
            }
            #pragma unroll
            for (int off = 8; off >= 1; off >>= 1)
                sum += __shfl_xor_sync(0xffffffffu, sum, off);
            float sc = __expf(m[i] - mnew);
            l[i] = l[i] * sc + sum;
            m[i] = mnew;
            ull sc2 = pack2(sc, sc);
            #pragma unroll
            for (int jc = 0; jc < 4; jc++)
                oacc[i][jc] = fmul2(oacc[i][jc], sc2);
        }
        __syncthreads();   // Ps visible to all

        // ---- O += P V (pack over output cols) ----
        const float* pbase = &Ps[(ty * 4) * 65];
        const float* vbase = &Vs[tx * 8];
        #pragma unroll 8
        for (int jp = 0; jp < 64; jp++) {
            ull vv[4];
            #pragma unroll
            for (int jc = 0; jc < 4; jc++)
                vv[jc] = *(const ull*)&vbase[jp * 128 + jc * 2];
            #pragma unroll
            for (int i = 0; i < 4; i++) {
                float p = pbase[i * 65 + jp];
                ull p2 = pack2(p, p);
                #pragma unroll
                for (int jc = 0; jc < 4; jc++)
                    oacc[i][jc] = ffma2(p2, vv[jc], oacc[i][jc]);
            }
        }
    }

    // epilogue: divide by l, store O
    float* Og = g_O + (size_t)(b * NTOK + q0) * ADIM;
    #pragma unroll
    for (int i = 0; i < 4; i++) {
        float inv = 1.0f / l[i];
        int row = ty * 4 + i;
        #pragma unroll
        for (int jc = 0; jc < 4; jc++) {
            float lo, hi; unpack2(oacc[i][jc], lo, hi);
            *(float2*)&Og[(size_t)row * ADIM + tx * 8 + jc * 2] =
                make_float2(lo * inv, hi * inv);
        }
    }
}

// =====================================================================
// Kernel 3: Y = O @ Wo, then * tanh(relu(1 + w_gamma[c])).
// M=16384, K=128, N=256.  BM=128, BN=128, BK=64, grid (128, 2).
// smem: Os[128][66] + Ws[64][128]
// =====================================================================
#define OUT_SMEM ((128*66 + 64*128) * 4)

__global__ __launch_bounds__(256)
void out_kernel(const float* __restrict__ Wo,
                const float* __restrict__ wg,
                float* __restrict__ Y) {
    extern __shared__ float sm[];
    float* Os = sm;                 // [128][66]
    float* Ws = sm + 128 * 66;      // [64][128]

    const int tid = threadIdx.x;
    const int tx = tid & 15;
    const int ty = tid >> 4;
    const int row0 = blockIdx.x * 128;
    const int col0 = blockIdx.y * 128;

    ull acc[8][4];
    #pragma unroll
    for (int i = 0; i < 8; i++)
        #pragma unroll
        for (int j = 0; j < 4; j++) acc[i][j] = 0ull;

    for (int kc = 0; kc < ADIM; kc += 64) {
        #pragma unroll
        for (int it = 0; it < 8; it++) {
            int i = tid + it * 256;
            int r = i >> 4;
            int c = (i & 15) << 2;
            float4 v = *(const float4*)&g_O[(size_t)(row0 + r) * ADIM + kc + c];
            float* d = &Os[r * 66 + c];
            *(float2*)d = make_float2(v.x, v.y);
            *(float2*)(d + 2) = make_float2(v.z, v.w);
        }
        #pragma unroll
        for (int it = 0; it < 8; it++) {
            int i = tid + it * 256;
            int r = i >> 5;
            int c = (i & 31) << 2;
            *(float4*)&Ws[r * 128 + c] =
                *(const float4*)&Wo[(size_t)(kc + r) * CIN + col0 + c];
        }
        __syncthreads();

        #pragma unroll 8
        for (int k = 0; k < 64; k++) {
            ull b[4];
            #pragma unroll
            for (int jc = 0; jc < 4; jc++)
                b[jc] = *(const ull*)&Ws[k * 128 + tx * 8 + jc * 2];
            #pragma unroll
            for (int i = 0; i < 8; i++) {
                float a = Os[(ty * 8 + i) * 66 + k];
                ull a2 = pack2(a, a);
                #pragma unroll
                for (int jc = 0; jc < 4; jc++)
                    acc[i][jc] = ffma2(a2, b[jc], acc[i][jc]);
            }
        }
        __syncthreads();
    }

    // epilogue: gamma scale + store
    float gam[8];
    #pragma unroll
    for (int jj = 0; jj < 8; jj++) {
        int c = col0 + tx * 8 + jj;
        gam[jj] = tanhf(fmaxf(1.0f + wg[c], 0.0f));
    }
    #pragma unroll
    for (int i = 0; i < 8; i++) {
        int row = row0 + ty * 8 + i;
        #pragma unroll
        for (int jc = 0; jc < 4; jc++) {
            float lo, hi; unpack2(acc[i][jc], lo, hi);
            lo *= gam[jc * 2]; hi *= gam[jc * 2 + 1];
            *(float2*)&Y[(size_t)row * CIN + col0 + tx * 8 + jc * 2] =
                make_float2(lo, hi);
        }
    }
}

// =====================================================================
extern "C" void kernel_launch(void* const* d_in, const int* in_sizes, int n_in,
                              void* d_out, int out_size) {
    const float* x  = (const float*)d_in[0];
    const float* Wq = (const float*)d_in[1];
    const float* Wk = (const float*)d_in[2];
    const float* Wv = (const float*)d_in[3];
    const float* Wo = (const float*)d_in[4];
    const float* wg = (const float*)d_in[5];
    float* y = (float*)d_out;

    static bool attrs_set = []() {
        cudaFuncSetAttribute(qkv_kernel, cudaFuncAttributeMaxDynamicSharedMemorySize, QKV_SMEM);
        cudaFuncSetAttribute(attn_kernel, cudaFuncAttributeMaxDynamicSharedMemorySize, ATTN_SMEM);
        cudaFuncSetAttribute(out_kernel, cudaFuncAttributeMaxDynamicSharedMemorySize, OUT_SMEM);
        return true;
    }();
    (void)attrs_set;

    qkv_kernel<<<dim3(MTOT / 128, 1, 3), 256, QKV_SMEM>>>(x, Wq, Wk, Wv);
    attn_kernel<<<dim3(NTOK / 64, BATCH), 256, ATTN_SMEM>>>();
    out_kernel<<<dim3(MTOT / 128, CIN / 128), 256, OUT_SMEM>>>(Wo, wg, y);
}

// round 4
// speedup vs baseline: 4.1968x; 4.1968x over previous
#include <cuda_runtime.h>
#include <cuda_bf16.h>
#include <math_constants.h>
#include <stdint.h>

#define BATCH 4
#define NTOK 4096
#define CIN 256
#define ADIM 128
#define MTOT (BATCH*NTOK)
#define NEG_SLOPE 0.2f

// ---------------- scratch ----------------
__device__ __nv_bfloat16 g_Qh[MTOT * ADIM];
__device__ __nv_bfloat16 g_Ql[MTOT * ADIM];
__device__ __nv_bfloat16 g_Kh[MTOT * ADIM];
__device__ __nv_bfloat16 g_Kl[MTOT * ADIM];
__device__ __nv_bfloat16 g_Vh[MTOT * ADIM];
__device__ __nv_bfloat16 g_Vl[MTOT * ADIM];
__device__ float g_O[MTOT * ADIM];

typedef unsigned long long ull;
__device__ __forceinline__ ull pack2(float lo, float hi) {
    ull r; asm("mov.b64 %0, {%1,%2};" : "=l"(r) : "f"(lo), "f"(hi)); return r;
}
__device__ __forceinline__ void unpack2(ull v, float &lo, float &hi) {
    asm("mov.b64 {%0,%1}, %2;" : "=f"(lo), "=f"(hi) : "l"(v));
}
__device__ __forceinline__ ull ffma2(ull a, ull b, ull c) {
    ull d; asm("fma.rn.f32x2 %0, %1, %2, %3;" : "=l"(d) : "l"(a), "l"(b), "l"(c)); return d;
}
__device__ __forceinline__ float lrelu(float x) { return x >= 0.0f ? x : NEG_SLOPE * x; }

// ---------------- warp-mma helpers ----------------
__device__ __forceinline__ uint32_t smem_u32(const void* p) {
    uint32_t a;
    asm("{ .reg .u64 t; cvta.to.shared.u64 t, %1; cvt.u32.u64 %0, t; }" : "=r"(a) : "l"(p));
    return a;
}
__device__ __forceinline__ void cp16(uint32_t dst, const void* src) {
    asm volatile("cp.async.cg.shared.global [%0], [%1], 16;" :: "r"(dst), "l"(src));
}
__device__ __forceinline__ void cp_commit() { asm volatile("cp.async.commit_group;" ::: "memory"); }
__device__ __forceinline__ void cp_wait0() { asm volatile("cp.async.wait_group 0;" ::: "memory"); }
__device__ __forceinline__ void cp_wait1() { asm volatile("cp.async.wait_group 1;" ::: "memory"); }

__device__ __forceinline__ void ldsm4(uint32_t* r, uint32_t a) {
    asm volatile("ldmatrix.sync.aligned.m8n8.x4.shared.b16 {%0,%1,%2,%3}, [%4];"
        : "=r"(r[0]), "=r"(r[1]), "=r"(r[2]), "=r"(r[3]) : "r"(a));
}
__device__ __forceinline__ void ldsm4t(uint32_t* r, uint32_t a) {
    asm volatile("ldmatrix.sync.aligned.m8n8.x4.trans.shared.b16 {%0,%1,%2,%3}, [%4];"
        : "=r"(r[0]), "=r"(r[1]), "=r"(r[2]), "=r"(r[3]) : "r"(a));
}
__device__ __forceinline__ void mma_bf16(float* d, const uint32_t* a, const uint32_t* b) {
    asm volatile(
        "mma.sync.aligned.m16n8k16.row.col.f32.bf16.bf16.f32 "
        "{%0,%1,%2,%3}, {%4,%5,%6,%7}, {%8,%9}, {%0,%1,%2,%3};"
        : "+f"(d[0]), "+f"(d[1]), "+f"(d[2]), "+f"(d[3])
        : "r"(a[0]), "r"(a[1]), "r"(a[2]), "r"(a[3]), "r"(b[0]), "r"(b[1]));
}
__device__ __forceinline__ uint32_t bf2bits(__nv_bfloat162 v) {
    return *(uint32_t*)&v;
}

// =====================================================================
// Kernel 1: QKV projection, fp32 GEMM; epilogue: leaky-relu + bf16 hi/lo.
// grid (128, 1, 3), 256 threads.
// =====================================================================
#define QKV_SMEM ((128*66 + 64*128) * 4)

__global__ __launch_bounds__(256)
void qkv_kernel(const float* __restrict__ X,
                const float* __restrict__ Wq,
                const float* __restrict__ Wk,
                const float* __restrict__ Wv) {
    extern __shared__ float sm[];
    float* Xs = sm;
    float* Ws = sm + 128 * 66;

    const float* Wsel = (blockIdx.z == 0) ? Wq : (blockIdx.z == 1) ? Wk : Wv;
    const int tid = threadIdx.x;
    const int tx = tid & 15;
    const int ty = tid >> 4;
    const int row0 = blockIdx.x * 128;

    ull acc[8][4];
    #pragma unroll
    for (int i = 0; i < 8; i++)
        #pragma unroll
        for (int j = 0; j < 4; j++) acc[i][j] = 0ull;

    for (int kc = 0; kc < CIN; kc += 64) {
        #pragma unroll
        for (int it = 0; it < 8; it++) {
            int i = tid + it * 256;
            int r = i >> 4, c = (i & 15) << 2;
            float4 v = *(const float4*)&X[(size_t)(row0 + r) * CIN + kc + c];
            float* d = &Xs[r * 66 + c];
            *(float2*)d = make_float2(v.x, v.y);
            *(float2*)(d + 2) = make_float2(v.z, v.w);
        }
        #pragma unroll
        for (int it = 0; it < 8; it++) {
            int i = tid + it * 256;
            int r = i >> 5, c = (i & 31) << 2;
            *(float4*)&Ws[r * 128 + c] = *(const float4*)&Wsel[(size_t)(kc + r) * ADIM + c];
        }
        __syncthreads();
        #pragma unroll 8
        for (int k = 0; k < 64; k++) {
            ull b[4];
            #pragma unroll
            for (int jc = 0; jc < 4; jc++) b[jc] = *(const ull*)&Ws[k * 128 + tx * 8 + jc * 2];
            #pragma unroll
            for (int i = 0; i < 8; i++) {
                float a = Xs[(ty * 8 + i) * 66 + k];
                ull a2 = pack2(a, a);
                #pragma unroll
                for (int jc = 0; jc < 4; jc++) acc[i][jc] = ffma2(a2, b[jc], acc[i][jc]);
            }
        }
        __syncthreads();
    }

    __nv_bfloat16* OH = (blockIdx.z == 0) ? g_Qh : (blockIdx.z == 1) ? g_Kh : g_Vh;
    __nv_bfloat16* OL = (blockIdx.z == 0) ? g_Ql : (blockIdx.z == 1) ? g_Kl : g_Vl;
    #pragma unroll
    for (int i = 0; i < 8; i++) {
        int row = row0 + ty * 8 + i;
        #pragma unroll
        for (int jc = 0; jc < 4; jc++) {
            float f0, f1; unpack2(acc[i][jc], f0, f1);
            f0 = lrelu(f0); f1 = lrelu(f1);
            __nv_bfloat162 hb = __floats2bfloat162_rn(f0, f1);
            __nv_bfloat162 lb = __floats2bfloat162_rn(f0 - __bfloat162float(hb.x),
                                                      f1 - __bfloat162float(hb.y));
            size_t o = (size_t)row * ADIM + tx * 8 + jc * 2;
            *(__nv_bfloat162*)&OH[o] = hb;
            *(__nv_bfloat162*)&OL[o] = lb;
        }
    }
}

// =====================================================================
// Kernel 2: flash attention via mma.sync bf16 (3xBF16 split precision).
// grid (32, 4), 256 threads. Warp w owns q rows [16w, 16w+16).
// smem: Qh[128x128] Ql[128x128], double-buffered {Kh,Kl,Vh,Vl}[64x128].
// Tiles stored as 16B chunks with XOR swizzle: off = row*256 + ((c ^ (row&7))<<4)
// =====================================================================
#define SQH 0
#define SQL 32768
#define SKV 65536           // + buf*65536 ; inside: Kh 0 | Kl 16384 | Vh 32768 | Vl 49152
#define ATTN_SMEM (65536 + 2*65536)

__device__ __forceinline__ void load_kv(uint32_t dst, const __nv_bfloat16* kh,
                                        const __nv_bfloat16* kl, const __nv_bfloat16* vh,
                                        const __nv_bfloat16* vl, int tid) {
    #pragma unroll
    for (int i = 0; i < 4; i++) {
        int lin = tid + i * 256;            // 1024 chunks of 16B per sub-tile
        int r = lin >> 4, c = lin & 15;
        uint32_t off = (uint32_t)(r * 256 + ((c ^ (r & 7)) << 4));
        size_t g = (size_t)r * ADIM + c * 8;
        cp16(dst + off, kh + g);
        cp16(dst + 16384 + off, kl + g);
        cp16(dst + 32768 + off, vh + g);
        cp16(dst + 49152 + off, vl + g);
    }
}

__global__ __launch_bounds__(256, 1)
void attn_kernel() {
    extern __shared__ char smc[];
    const uint32_t sb = smem_u32(smc);
    const int tid = threadIdx.x;
    const int w = tid >> 5;
    const int lane = tid & 31;
    const int b = blockIdx.y;
    const int q0 = blockIdx.x * 128;

    // ---- load Q (hi+lo) ----
    {
        const __nv_bfloat16* qh = g_Qh + (size_t)(b * NTOK + q0) * ADIM;
        const __nv_bfloat16* ql = g_Ql + (size_t)(b * NTOK + q0) * ADIM;
        #pragma unroll
        for (int i = 0; i < 8; i++) {
            int lin = tid + i * 256;        // 2048 chunks
            int r = lin >> 4, c = lin & 15;
            uint32_t off = (uint32_t)(r * 256 + ((c ^ (r & 7)) << 4));
            size_t g = (size_t)r * ADIM + c * 8;
            cp16(sb + SQH + off, qh + g);
            cp16(sb + SQL + off, ql + g);
        }
    }
    const __nv_bfloat16* KHb = g_Kh + (size_t)b * NTOK * ADIM;
    const __nv_bfloat16* KLb = g_Kl + (size_t)b * NTOK * ADIM;
    const __nv_bfloat16* VHb = g_Vh + (size_t)b * NTOK * ADIM;
    const __nv_bfloat16* VLb = g_Vl + (size_t)b * NTOK * ADIM;
    load_kv(sb + SKV, KHb, KLb, VHb, VLb, tid);
    cp_commit();

    // lane-derived ldmatrix address components
    const int rowa = 16 * w + (lane & 15);          // A (Q) rows
    const uint32_t qro = (uint32_t)rowa * 256;
    const int ca = lane >> 4;                       // 0/1 : k-chunk select
    const int swa = rowa & 7;

    const int rowb = (lane & 7) + ((lane & 16) >> 1);  // B (K) row within 16-row pair
    const int cb = (lane >> 3) & 1;
    const int swb = rowb & 7;

    const int rowv = (lane & 7) + (lane & 8);          // B (V, trans) row within 16
    const int cv = (lane >> 4) & 1;
    const int swv = rowv & 7;

    float oacc[16][4];
    #pragma unroll
    for (int nb = 0; nb < 16; nb++)
        #pragma unroll
        for (int i = 0; i < 4; i++) oacc[nb][i] = 0.0f;
    float m0 = -CUDART_INF_F, m8 = -CUDART_INF_F, l0 = 0.0f, l8 = 0.0f;

    #pragma unroll 1
    for (int t = 0; t < 64; t++) {
        __syncthreads();   // all warps done reading the buffer we are about to overwrite
        if (t < 63) {
            uint32_t nb_ = sb + SKV + (uint32_t)((t + 1) & 1) * 65536u;
            size_t o = (size_t)(t + 1) * 64 * ADIM;
            load_kv(nb_, KHb + o, KLb + o, VHb + o, VLb + o, tid);
            cp_commit();
            cp_wait1();
        } else {
            cp_wait0();
        }
        __syncthreads();

        const uint32_t KB = sb + SKV + (uint32_t)(t & 1) * 65536u;
        const uint32_t VB = KB + 32768u;

        // ---- S = Qh*Kh^T + Qh*Kl^T + Ql*Kh^T ----
        float sacc[8][4];
        #pragma unroll
        for (int nb = 0; nb < 8; nb++)
            #pragma unroll
            for (int i = 0; i < 4; i++) sacc[nb][i] = 0.0f;

        #pragma unroll
        for (int ks = 0; ks < 8; ks++) {
            uint32_t aqh[4], aql[4];
            uint32_t ach = (uint32_t)(((2 * ks + ca) ^ swa) << 4);
            ldsm4(aqh, sb + SQH + qro + ach);
            ldsm4(aql, sb + SQL + qro + ach);
            uint32_t bch = (uint32_t)(((2 * ks + cb) ^ swb) << 4);
            #pragma unroll
            for (int jp = 0; jp < 4; jp++) {
                uint32_t bh[4], bl[4];
                uint32_t boff = (uint32_t)((16 * jp + rowb) * 256) + bch;
                ldsm4(bh, KB + boff);
                ldsm4(bl, KB + 16384u + boff);
                mma_bf16(sacc[2 * jp],     aqh, bh);
                mma_bf16(sacc[2 * jp + 1], aqh, bh + 2);
                mma_bf16(sacc[2 * jp],     aqh, bl);
                mma_bf16(sacc[2 * jp + 1], aqh, bl + 2);
                mma_bf16(sacc[2 * jp],     aql, bh);
                mma_bf16(sacc[2 * jp + 1], aql, bh + 2);
            }
        }

        // ---- online softmax (rows r=lane/4 and r+8; quad = lanes sharing a row) ----
        float rm0 = sacc[0][0], rm8 = sacc[0][2];
        #pragma unroll
        for (int nb = 0; nb < 8; nb++) {
            rm0 = fmaxf(rm0, fmaxf(sacc[nb][0], sacc[nb][1]));
            rm8 = fmaxf(rm8, fmaxf(sacc[nb][2], sacc[nb][3]));
        }
        rm0 = fmaxf(rm0, __shfl_xor_sync(0xffffffffu, rm0, 1));
        rm0 = fmaxf(rm0, __shfl_xor_sync(0xffffffffu, rm0, 2));
        rm8 = fmaxf(rm8, __shfl_xor_sync(0xffffffffu, rm8, 1));
        rm8 = fmaxf(rm8, __shfl_xor_sync(0xffffffffu, rm8, 2));
        float mn0 = fmaxf(m0, rm0), mn8 = fmaxf(m8, rm8);
        float sc0 = __expf(m0 - mn0), sc8 = __expf(m8 - mn8);
        m0 = mn0; m8 = mn8;

        uint32_t ph[8][2], pl[8][2];
        float ls0 = 0.0f, ls8 = 0.0f;
        #pragma unroll
        for (int nb = 0; nb < 8; nb++) {
            float p0 = __expf(sacc[nb][0] - mn0);
            float p1 = __expf(sacc[nb][1] - mn0);
            float p2 = __expf(sacc[nb][2] - mn8);
            float p3 = __expf(sacc[nb][3] - mn8);
            ls0 += p0 + p1; ls8 += p2 + p3;
            __nv_bfloat162 h01 = __floats2bfloat162_rn(p0, p1);
            __nv_bfloat162 h23 = __floats2bfloat162_rn(p2, p3);
            ph[nb][0] = bf2bits(h01);
            ph[nb][1] = bf2bits(h23);
            __nv_bfloat162 l01 = __floats2bfloat162_rn(p0 - __bfloat162float(h01.x),
                                                       p1 - __bfloat162float(h01.y));
            __nv_bfloat162 l23 = __floats2bfloat162_rn(p2 - __bfloat162float(h23.x),
                                                       p3 - __bfloat162float(h23.y));
            pl[nb][0] = bf2bits(l01);
            pl[nb][1] = bf2bits(l23);
        }
        l0 = l0 * sc0 + ls0;
        l8 = l8 * sc8 + ls8;
        #pragma unroll
        for (int nb = 0; nb < 16; nb++) {
            oacc[nb][0] *= sc0; oacc[nb][1] *= sc0;
            oacc[nb][2] *= sc8; oacc[nb][3] *= sc8;
        }

        // ---- O += Ph*Vh + Ph*Vl + Pl*Vh ----
        #pragma unroll
        for (int ks = 0; ks < 4; ks++) {
            uint32_t ah[4] = { ph[2 * ks][0], ph[2 * ks][1], ph[2 * ks + 1][0], ph[2 * ks + 1][1] };
            uint32_t al[4] = { pl[2 * ks][0], pl[2 * ks][1], pl[2 * ks + 1][0], pl[2 * ks + 1][1] };
            uint32_t vro = (uint32_t)((16 * ks + rowv) * 256);
            #pragma unroll
            for (int jp = 0; jp < 8; jp++) {
                uint32_t bh[4], bl[4];
                uint32_t voff = vro + (uint32_t)(((2 * jp + cv) ^ swv) << 4);
                ldsm4t(bh, VB + voff);
                ldsm4t(bl, VB + 16384u + voff);
                mma_bf16(oacc[2 * jp],     ah, bh);
                mma_bf16(oacc[2 * jp + 1], ah, bh + 2);
                mma_bf16(oacc[2 * jp],     ah, bl);
                mma_bf16(oacc[2 * jp + 1], ah, bl + 2);
                mma_bf16(oacc[2 * jp],     al, bh);
                mma_bf16(oacc[2 * jp + 1], al, bh + 2);
            }
        }
    }

    // ---- epilogue ----
    l0 += __shfl_xor_sync(0xffffffffu, l0, 1);
    l0 += __shfl_xor_sync(0xffffffffu, l0, 2);
    l8 += __shfl_xor_sync(0xffffffffu, l8, 1);
    l8 += __shfl_xor_sync(0xffffffffu, l8, 2);
    float inv0 = 1.0f / l0, inv8 = 1.0f / l8;
    int r0 = q0 + 16 * w + (lane >> 2);
    int cb2 = 2 * (lane & 3);
    float* O = g_O + ((size_t)b * NTOK + r0) * ADIM;
    #pragma unroll
    for (int nb = 0; nb < 16; nb++) {
        int c = nb * 8 + cb2;
        *(float2*)&O[c] = make_float2(oacc[nb][0] * inv0, oacc[nb][1] * inv0);
        *(float2*)&O[c + 8 * ADIM] = make_float2(oacc[nb][2] * inv8, oacc[nb][3] * inv8);
    }
}

// =====================================================================
// Kernel 3: Y = O @ Wo * tanh(relu(1+wg)). fp32.
// =====================================================================
#define OUT_SMEM ((128*66 + 64*128) * 4)

__global__ __launch_bounds__(256)
void out_kernel(const float* __restrict__ Wo,
                const float* __restrict__ wgm,
                float* __restrict__ Y) {
    extern __shared__ float sm[];
    float* Os = sm;
    float* Ws = sm + 128 * 66;
    const int tid = threadIdx.x;
    const int tx = tid & 15;
    const int ty = tid >> 4;
    const int row0 = blockIdx.x * 128;
    const int col0 = blockIdx.y * 128;

    ull acc[8][4];
    #pragma unroll
    for (int i = 0; i < 8; i++)
        #pragma unroll
        for (int j = 0; j < 4; j++) acc[i][j] = 0ull;

    for (int kc = 0; kc < ADIM; kc += 64) {
        #pragma unroll
        for (int it = 0; it < 8; it++) {
            int i = tid + it * 256;
            int r = i >> 4, c = (i & 15) << 2;
            float4 v = *(const float4*)&g_O[(size_t)(row0 + r) * ADIM + kc + c];
            float* d = &Os[r * 66 + c];
            *(float2*)d = make_float2(v.x, v.y);
            *(float2*)(d + 2) = make_float2(v.z, v.w);
        }
        #pragma unroll
        for (int it = 0; it < 8; it++) {
            int i = tid + it * 256;
            int r = i >> 5, c = (i & 31) << 2;
            *(float4*)&Ws[r * 128 + c] = *(const float4*)&Wo[(size_t)(kc + r) * CIN + col0 + c];
        }
        __syncthreads();
        #pragma unroll 8
        for (int k = 0; k < 64; k++) {
            ull b[4];
            #pragma unroll
            for (int jc = 0; jc < 4; jc++) b[jc] = *(const ull*)&Ws[k * 128 + tx * 8 + jc * 2];
            #pragma unroll
            for (int i = 0; i < 8; i++) {
                float a = Os[(ty * 8 + i) * 66 + k];
                ull a2 = pack2(a, a);
                #pragma unroll
                for (int jc = 0; jc < 4; jc++) acc[i][jc] = ffma2(a2, b[jc], acc[i][jc]);
            }
        }
        __syncthreads();
    }

    float gam[8];
    #pragma unroll
    for (int jj = 0; jj < 8; jj++)
        gam[jj] = tanhf(fmaxf(1.0f + wgm[col0 + tx * 8 + jj], 0.0f));
    #pragma unroll
    for (int i = 0; i < 8; i++) {
        int rw = row0 + ty * 8 + i;
        #pragma unroll
        for (int jc = 0; jc < 4; jc++) {
            float lo, hi; unpack2(acc[i][jc], lo, hi);
            *(float2*)&Y[(size_t)rw * CIN + col0 + tx * 8 + jc * 2] =
                make_float2(lo * gam[jc * 2], hi * gam[jc * 2 + 1]);
        }
    }
}

// =====================================================================
extern "C" void kernel_launch(void* const* d_in, const int* in_sizes, int n_in,
                              void* d_out, int out_size) {
    const float* x  = (const float*)d_in[0];
    const float* Wq = (const float*)d_in[1];
    const float* Wk = (const float*)d_in[2];
    const float* Wv = (const float*)d_in[3];
    const float* Wo = (const float*)d_in[4];
    const float* wg = (const float*)d_in[5];
    float* y = (float*)d_out;

    static bool attrs_set = []() {
        cudaFuncSetAttribute(qkv_kernel, cudaFuncAttributeMaxDynamicSharedMemorySize, QKV_SMEM);
        cudaFuncSetAttribute(attn_kernel, cudaFuncAttributeMaxDynamicSharedMemorySize, ATTN_SMEM);
        cudaFuncSetAttribute(out_kernel, cudaFuncAttributeMaxDynamicSharedMemorySize, OUT_SMEM);
        return true;
    }();
    (void)attrs_set;

    qkv_kernel<<<dim3(MTOT / 128, 1, 3), 256, QKV_SMEM>>>(x, Wq, Wk, Wv);
    attn_kernel<<<dim3(NTOK / 128, BATCH), 256, ATTN_SMEM>>>();
    out_kernel<<<dim3(MTOT / 128, CIN / 128), 256, OUT_SMEM>>>(Wo, wg, y);
}

// round 5
// speedup vs baseline: 5.2352x; 1.2474x over previous
#include <cuda_runtime.h>
#include <cuda_bf16.h>
#include <math_constants.h>
#include <stdint.h>

#define BATCH 4
#define NTOK 4096
#define CIN 256
#define ADIM 128
#define MTOT (BATCH*NTOK)
#define NEG_SLOPE 0.2f

// ---------------- scratch ----------------
__device__ __nv_bfloat16 g_Xh[MTOT * CIN];
__device__ __nv_bfloat16 g_Xl[MTOT * CIN];
__device__ __nv_bfloat16 g_Qh[MTOT * ADIM];
__device__ __nv_bfloat16 g_Ql[MTOT * ADIM];
__device__ __nv_bfloat16 g_Kh[MTOT * ADIM];
__device__ __nv_bfloat16 g_Kl[MTOT * ADIM];
__device__ __nv_bfloat16 g_Vh[MTOT * ADIM];
__device__ __nv_bfloat16 g_Vl[MTOT * ADIM];
__device__ __nv_bfloat16 g_Oh[MTOT * ADIM];
__device__ __nv_bfloat16 g_Ol[MTOT * ADIM];
__device__ __nv_bfloat16 g_Wqh[CIN * ADIM], g_Wql[CIN * ADIM];
__device__ __nv_bfloat16 g_Wkh[CIN * ADIM], g_Wkl[CIN * ADIM];
__device__ __nv_bfloat16 g_Wvh[CIN * ADIM], g_Wvl[CIN * ADIM];
__device__ __nv_bfloat16 g_Woh[ADIM * CIN], g_Wol[ADIM * CIN];

__device__ __forceinline__ float lrelu(float x) { return x >= 0.0f ? x : NEG_SLOPE * x; }

// ---------------- helpers ----------------
__device__ __forceinline__ uint32_t smem_u32(const void* p) {
    uint32_t a;
    asm("{ .reg .u64 t; cvta.to.shared.u64 t, %1; cvt.u32.u64 %0, t; }" : "=r"(a) : "l"(p));
    return a;
}
__device__ __forceinline__ void cp16(uint32_t dst, const void* src) {
    asm volatile("cp.async.cg.shared.global [%0], [%1], 16;" :: "r"(dst), "l"(src));
}
__device__ __forceinline__ void cp_commit() { asm volatile("cp.async.commit_group;" ::: "memory"); }
__device__ __forceinline__ void cp_wait0() { asm volatile("cp.async.wait_group 0;" ::: "memory"); }
__device__ __forceinline__ void cp_wait1() { asm volatile("cp.async.wait_group 1;" ::: "memory"); }

__device__ __forceinline__ void ldsm4(uint32_t* r, uint32_t a) {
    asm volatile("ldmatrix.sync.aligned.m8n8.x4.shared.b16 {%0,%1,%2,%3}, [%4];"
        : "=r"(r[0]), "=r"(r[1]), "=r"(r[2]), "=r"(r[3]) : "r"(a));
}
__device__ __forceinline__ void ldsm4t(uint32_t* r, uint32_t a) {
    asm volatile("ldmatrix.sync.aligned.m8n8.x4.trans.shared.b16 {%0,%1,%2,%3}, [%4];"
        : "=r"(r[0]), "=r"(r[1]), "=r"(r[2]), "=r"(r[3]) : "r"(a));
}
__device__ __forceinline__ void mma_bf16(float* d, const uint32_t* a, const uint32_t* b) {
    asm volatile(
        "mma.sync.aligned.m16n8k16.row.col.f32.bf16.bf16.f32 "
        "{%0,%1,%2,%3}, {%4,%5,%6,%7}, {%8,%9}, {%0,%1,%2,%3};"
        : "+f"(d[0]), "+f"(d[1]), "+f"(d[2]), "+f"(d[3])
        : "r"(a[0]), "r"(a[1]), "r"(a[2]), "r"(a[3]), "r"(b[0]), "r"(b[1]));
}
__device__ __forceinline__ uint32_t bf2bits(__nv_bfloat162 v) { return *(uint32_t*)&v; }

__device__ __forceinline__ void split2(float f0, float f1, __nv_bfloat162& h, __nv_bfloat162& l) {
    h = __floats2bfloat162_rn(f0, f1);
    l = __floats2bfloat162_rn(f0 - __bfloat162float(h.x), f1 - __bfloat162float(h.y));
}

// =====================================================================
// Convert kernels: fp32 -> bf16 hi/lo
// =====================================================================
__global__ __launch_bounds__(256)
void convx_kernel(const float* __restrict__ X) {
    int i = blockIdx.x * 256 + threadIdx.x;       // 1048576 float4s
    float4 v = ((const float4*)X)[i];
    __nv_bfloat162 h0, l0, h1, l1;
    split2(v.x, v.y, h0, l0);
    split2(v.z, v.w, h1, l1);
    ((__nv_bfloat162*)g_Xh)[2 * i] = h0;
    ((__nv_bfloat162*)g_Xh)[2 * i + 1] = h1;
    ((__nv_bfloat162*)g_Xl)[2 * i] = l0;
    ((__nv_bfloat162*)g_Xl)[2 * i + 1] = l1;
}

__global__ __launch_bounds__(256)
void convw_kernel(const float* __restrict__ Wq, const float* __restrict__ Wk,
                  const float* __restrict__ Wv, const float* __restrict__ Wo) {
    int j = blockIdx.x * 256 + threadIdx.x;       // 32768 float4s total
    int sel = j >> 13;                            // 8192 float4 per weight
    int loc = j & 8191;
    const float* src = (sel == 0) ? Wq : (sel == 1) ? Wk : (sel == 2) ? Wv : Wo;
    __nv_bfloat16* dh = (sel == 0) ? g_Wqh : (sel == 1) ? g_Wkh : (sel == 2) ? g_Wvh : g_Woh;
    __nv_bfloat16* dl = (sel == 0) ? g_Wql : (sel == 1) ? g_Wkl : (sel == 2) ? g_Wvl : g_Wol;
    float4 v = ((const float4*)src)[loc];
    __nv_bfloat162 h0, l0, h1, l1;
    split2(v.x, v.y, h0, l0);
    split2(v.z, v.w, h1, l1);
    ((__nv_bfloat162*)dh)[2 * loc] = h0;
    ((__nv_bfloat162*)dh)[2 * loc + 1] = h1;
    ((__nv_bfloat162*)dl)[2 * loc] = l0;
    ((__nv_bfloat162*)dl)[2 * loc + 1] = l1;
}

// =====================================================================
// Kernel 1: QKV projection via mma.sync, 3xBF16 split.
// grid (128, 3), 256 threads. CTA: 128 rows x 128 cols, K=256 in 4 chunks of 64.
// =====================================================================
#define QKV2_XH 0
#define QKV2_XL 16384
#define QKV2_WH 32768
#define QKV2_WL 49152
#define QKV2_SMEM 65536

__global__ __launch_bounds__(256)
void qkv2_kernel() {
    extern __shared__ char smc[];
    const uint32_t sb = smem_u32(smc);
    const int tid = threadIdx.x;
    const int w = tid >> 5;
    const int lane = tid & 31;
    const int row0 = blockIdx.x * 128;

    const __nv_bfloat16 *WH, *WL;
    __nv_bfloat16 *OH, *OL;
    if (blockIdx.y == 0)      { WH = g_Wqh; WL = g_Wql; OH = g_Qh; OL = g_Ql; }
    else if (blockIdx.y == 1) { WH = g_Wkh; WL = g_Wkl; OH = g_Kh; OL = g_Kl; }
    else                      { WH = g_Wvh; WL = g_Wvl; OH = g_Vh; OL = g_Vl; }

    const int rowa = 16 * w + (lane & 15);
    const int ca = lane >> 4, swa = rowa & 7;
    const int rowv = (lane & 7) + (lane & 8);
    const int cv = (lane >> 4) & 1, swv = rowv & 7;

    float oacc[16][4];
    #pragma unroll
    for (int nb = 0; nb < 16; nb++)
        #pragma unroll
        for (int i = 0; i < 4; i++) oacc[nb][i] = 0.0f;

    #pragma unroll 1
    for (int kc = 0; kc < 4; kc++) {
        #pragma unroll
        for (int i = 0; i < 4; i++) {           // X chunk [128 x 64]
            int lin = tid + i * 256;            // 1024 chunks
            int r = lin >> 3, c = lin & 7;
            uint32_t off = (uint32_t)(r * 128 + ((c ^ (r & 7)) << 4));
            size_t g = (size_t)(row0 + r) * CIN + kc * 64 + c * 8;
            cp16(sb + QKV2_XH + off, g_Xh + g);
            cp16(sb + QKV2_XL + off, g_Xl + g);
        }
        #pragma unroll
        for (int i = 0; i < 4; i++) {           // W chunk [64 x 128]
            int lin = tid + i * 256;
            int r = lin >> 4, c = lin & 15;
            uint32_t off = (uint32_t)(r * 256 + ((c ^ (r & 7)) << 4));
            size_t g = (size_t)(kc * 64 + r) * ADIM + c * 8;
            cp16(sb + QKV2_WH + off, WH + g);
            cp16(sb + QKV2_WL + off, WL + g);
        }
        cp_commit(); cp_wait0();
        __syncthreads();
        #pragma unroll
        for (int ks = 0; ks < 4; ks++) {
            uint32_t ah[4], al[4];
            uint32_t ach = (uint32_t)(((2 * ks + ca) ^ swa) << 4);
            ldsm4(ah, sb + QKV2_XH + rowa * 128 + ach);
            ldsm4(al, sb + QKV2_XL + rowa * 128 + ach);
            #pragma unroll
            for (int jp = 0; jp < 8; jp++) {
                uint32_t bh[4], bl[4];
                uint32_t boff = (uint32_t)((16 * ks + rowv) * 256 + (((2 * jp + cv) ^ swv) << 4));
                ldsm4t(bh, sb + QKV2_WH + boff);
                ldsm4t(bl, sb + QKV2_WL + boff);
                mma_bf16(oacc[2 * jp],     ah, bh); mma_bf16(oacc[2 * jp + 1], ah, bh + 2);
                mma_bf16(oacc[2 * jp],     ah, bl); mma_bf16(oacc[2 * jp + 1], ah, bl + 2);
                mma_bf16(oacc[2 * jp],     al, bh); mma_bf16(oacc[2 * jp + 1], al, bh + 2);
            }
        }
        __syncthreads();
    }

    const int r0 = row0 + 16 * w + (lane >> 2);
    const int cb2 = 2 * (lane & 3);
    #pragma unroll
    for (int nb = 0; nb < 16; nb++) {
        int c = nb * 8 + cb2;
        __nv_bfloat162 h01, l01, h23, l23;
        split2(lrelu(oacc[nb][0]), lrelu(oacc[nb][1]), h01, l01);
        split2(lrelu(oacc[nb][2]), lrelu(oacc[nb][3]), h23, l23);
        *(__nv_bfloat162*)&OH[(size_t)r0 * ADIM + c] = h01;
        *(__nv_bfloat162*)&OL[(size_t)r0 * ADIM + c] = l01;
        *(__nv_bfloat162*)&OH[(size_t)(r0 + 8) * ADIM + c] = h23;
        *(__nv_bfloat162*)&OL[(size_t)(r0 + 8) * ADIM + c] = l23;
    }
}

// =====================================================================
// Kernel 2: flash attention via mma.sync bf16 (3xBF16 split precision).
// grid (32, 4), 256 threads. Warp w owns q rows [16w, 16w+16).
// =====================================================================
#define SQH 0
#define SQL 32768
#define SKV 65536
#define ATTN_SMEM (65536 + 2*65536)

__device__ __forceinline__ void load_kv(uint32_t dst, const __nv_bfloat16* kh,
                                        const __nv_bfloat16* kl, const __nv_bfloat16* vh,
                                        const __nv_bfloat16* vl, int tid) {
    #pragma unroll
    for (int i = 0; i < 4; i++) {
        int lin = tid + i * 256;
        int r = lin >> 4, c = lin & 15;
        uint32_t off = (uint32_t)(r * 256 + ((c ^ (r & 7)) << 4));
        size_t g = (size_t)r * ADIM + c * 8;
        cp16(dst + off, kh + g);
        cp16(dst + 16384 + off, kl + g);
        cp16(dst + 32768 + off, vh + g);
        cp16(dst + 49152 + off, vl + g);
    }
}

__global__ __launch_bounds__(256, 1)
void attn_kernel() {
    extern __shared__ char smc[];
    const uint32_t sb = smem_u32(smc);
    const int tid = threadIdx.x;
    const int w = tid >> 5;
    const int lane = tid & 31;
    const int b = blockIdx.y;
    const int q0 = blockIdx.x * 128;

    {
        const __nv_bfloat16* qh = g_Qh + (size_t)(b * NTOK + q0) * ADIM;
        const __nv_bfloat16* ql = g_Ql + (size_t)(b * NTOK + q0) * ADIM;
        #pragma unroll
        for (int i = 0; i < 8; i++) {
            int lin = tid + i * 256;
            int r = lin >> 4, c = lin & 15;
            uint32_t off = (uint32_t)(r * 256 + ((c ^ (r & 7)) << 4));
            size_t g = (size_t)r * ADIM + c * 8;
            cp16(sb + SQH + off, qh + g);
            cp16(sb + SQL + off, ql + g);
        }
    }
    const __nv_bfloat16* KHb = g_Kh + (size_t)b * NTOK * ADIM;
    const __nv_bfloat16* KLb = g_Kl + (size_t)b * NTOK * ADIM;
    const __nv_bfloat16* VHb = g_Vh + (size_t)b * NTOK * ADIM;
    const __nv_bfloat16* VLb = g_Vl + (size_t)b * NTOK * ADIM;
    load_kv(sb + SKV, KHb, KLb, VHb, VLb, tid);
    cp_commit();

    const int rowa = 16 * w + (lane & 15);
    const uint32_t qro = (uint32_t)rowa * 256;
    const int ca = lane >> 4;
    const int swa = rowa & 7;
    const int rowb = (lane & 7) + ((lane & 16) >> 1);
    const int cb = (lane >> 3) & 1;
    const int swb = rowb & 7;
    const int rowv = (lane & 7) + (lane & 8);
    const int cv = (lane >> 4) & 1;
    const int swv = rowv & 7;

    float oacc[16][4];
    #pragma unroll
    for (int nb = 0; nb < 16; nb++)
        #pragma unroll
        for (int i = 0; i < 4; i++) oacc[nb][i] = 0.0f;
    float m0 = -CUDART_INF_F, m8 = -CUDART_INF_F, l0 = 0.0f, l8 = 0.0f;

    #pragma unroll 1
    for (int t = 0; t < 64; t++) {
        __syncthreads();
        if (t < 63) {
            uint32_t nb_ = sb + SKV + (uint32_t)((t + 1) & 1) * 65536u;
            size_t o = (size_t)(t + 1) * 64 * ADIM;
            load_kv(nb_, KHb + o, KLb + o, VHb + o, VLb + o, tid);
            cp_commit();
            cp_wait1();
        } else {
            cp_wait0();
        }
        __syncthreads();

        const uint32_t KB = sb + SKV + (uint32_t)(t & 1) * 65536u;
        const uint32_t VB = KB + 32768u;

        float sacc[8][4];
        #pragma unroll
        for (int nb = 0; nb < 8; nb++)
            #pragma unroll
            for (int i = 0; i < 4; i++) sacc[nb][i] = 0.0f;

        #pragma unroll
        for (int ks = 0; ks < 8; ks++) {
            uint32_t aqh[4], aql[4];
            uint32_t ach = (uint32_t)(((2 * ks + ca) ^ swa) << 4);
            ldsm4(aqh, sb + SQH + qro + ach);
            ldsm4(aql, sb + SQL + qro + ach);
            uint32_t bch = (uint32_t)(((2 * ks + cb) ^ swb) << 4);
            #pragma unroll
            for (int jp = 0; jp < 4; jp++) {
                uint32_t bh[4], bl[4];
                uint32_t boff = (uint32_t)((16 * jp + rowb) * 256) + bch;
                ldsm4(bh, KB + boff);
                ldsm4(bl, KB + 16384u + boff);
                mma_bf16(sacc[2 * jp],     aqh, bh);
                mma_bf16(sacc[2 * jp + 1], aqh, bh + 2);
                mma_bf16(sacc[2 * jp],     aqh, bl);
                mma_bf16(sacc[2 * jp + 1], aqh, bl + 2);
                mma_bf16(sacc[2 * jp],     aql, bh);
                mma_bf16(sacc[2 * jp + 1], aql, bh + 2);
            }
        }

        float rm0 = sacc[0][0], rm8 = sacc[0][2];
        #pragma unroll
        for (int nb = 0; nb < 8; nb++) {
            rm0 = fmaxf(rm0, fmaxf(sacc[nb][0], sacc[nb][1]));
            rm8 = fmaxf(rm8, fmaxf(sacc[nb][2], sacc[nb][3]));
        }
        rm0 = fmaxf(rm0, __shfl_xor_sync(0xffffffffu, rm0, 1));
        rm0 = fmaxf(rm0, __shfl_xor_sync(0xffffffffu, rm0, 2));
        rm8 = fmaxf(rm8, __shfl_xor_sync(0xffffffffu, rm8, 1));
        rm8 = fmaxf(rm8, __shfl_xor_sync(0xffffffffu, rm8, 2));
        float mn0 = fmaxf(m0, rm0), mn8 = fmaxf(m8, rm8);
        float sc0 = __expf(m0 - mn0), sc8 = __expf(m8 - mn8);
        m0 = mn0; m8 = mn8;

        uint32_t ph[8][2], pl[8][2];
        float ls0 = 0.0f, ls8 = 0.0f;
        #pragma unroll
        for (int nb = 0; nb < 8; nb++) {
            float p0 = __expf(sacc[nb][0] - mn0);
            float p1 = __expf(sacc[nb][1] - mn0);
            float p2 = __expf(sacc[nb][2] - mn8);
            float p3 = __expf(sacc[nb][3] - mn8);
            ls0 += p0 + p1; ls8 += p2 + p3;
            __nv_bfloat162 h01, l01, h23, l23;
            split2(p0, p1, h01, l01);
            split2(p2, p3, h23, l23);
            ph[nb][0] = bf2bits(h01);
            ph[nb][1] = bf2bits(h23);
            pl[nb][0] = bf2bits(l01);
            pl[nb][1] = bf2bits(l23);
        }
        l0 = l0 * sc0 + ls0;
        l8 = l8 * sc8 + ls8;
        #pragma unroll
        for (int nb = 0; nb < 16; nb++) {
            oacc[nb][0] *= sc0; oacc[nb][1] *= sc0;
            oacc[nb][2] *= sc8; oacc[nb][3] *= sc8;
        }

        #pragma unroll
        for (int ks = 0; ks < 4; ks++) {
            uint32_t ah[4] = { ph[2 * ks][0], ph[2 * ks][1], ph[2 * ks + 1][0], ph[2 * ks + 1][1] };
            uint32_t al[4] = { pl[2 * ks][0], pl[2 * ks][1], pl[2 * ks + 1][0], pl[2 * ks + 1][1] };
            uint32_t vro = (uint32_t)((16 * ks + rowv) * 256);
            #pragma unroll
            for (int jp = 0; jp < 8; jp++) {
                uint32_t bh[4], bl[4];
                uint32_t voff = vro + (uint32_t)(((2 * jp + cv) ^ swv) << 4);
                ldsm4t(bh, VB + voff);
                ldsm4t(bl, VB + 16384u + voff);
                mma_bf16(oacc[2 * jp],     ah, bh);
                mma_bf16(oacc[2 * jp + 1], ah, bh + 2);
                mma_bf16(oacc[2 * jp],     ah, bl);
                mma_bf16(oacc[2 * jp + 1], ah, bl + 2);
                mma_bf16(oacc[2 * jp],     al, bh);
                mma_bf16(oacc[2 * jp + 1], al, bh + 2);
            }
        }
    }

    l0 += __shfl_xor_sync(0xffffffffu, l0, 1);
    l0 += __shfl_xor_sync(0xffffffffu, l0, 2);
    l8 += __shfl_xor_sync(0xffffffffu, l8, 1);
    l8 += __shfl_xor_sync(0xffffffffu, l8, 2);
    float inv0 = 1.0f / l0, inv8 = 1.0f / l8;
    size_t r0 = (size_t)b * NTOK + q0 + 16 * w + (lane >> 2);
    int cb2 = 2 * (lane & 3);
    #pragma unroll
    for (int nb = 0; nb < 16; nb++) {
        int c = nb * 8 + cb2;
        __nv_bfloat162 h01, l01, h23, l23;
        split2(oacc[nb][0] * inv0, oacc[nb][1] * inv0, h01, l01);
        split2(oacc[nb][2] * inv8, oacc[nb][3] * inv8, h23, l23);
        *(__nv_bfloat162*)&g_Oh[r0 * ADIM + c] = h01;
        *(__nv_bfloat162*)&g_Ol[r0 * ADIM + c] = l01;
        *(__nv_bfloat162*)&g_Oh[(r0 + 8) * ADIM + c] = h23;
        *(__nv_bfloat162*)&g_Ol[(r0 + 8) * ADIM + c] = l23;
    }
}

// =====================================================================
// Kernel 3: Y = O @ Wo * tanh(relu(1+wg)) via mma.sync, 3xBF16 split.
// grid (128, 2), 256 threads. CTA: 128 rows x 128 cols, K=128 in 2 chunks.
// =====================================================================
#define OUT2_AH 0
#define OUT2_AL 16384
#define OUT2_WH 32768
#define OUT2_WL 49152
#define OUT2_SMEM 65536

__global__ __launch_bounds__(256)
void out2_kernel(const float* __restrict__ wgm, float* __restrict__ Y) {
    extern __shared__ char smc[];
    const uint32_t sb = smem_u32(smc);
    const int tid = threadIdx.x;
    const int w = tid >> 5;
    const int lane = tid & 31;
    const int row0 = blockIdx.x * 128;
    const int col0 = blockIdx.y * 128;

    const int rowa = 16 * w + (lane & 15);
    const int ca = lane >> 4, swa = rowa & 7;
    const int rowv = (lane & 7) + (lane & 8);
    const int cv = (lane >> 4) & 1, swv = rowv & 7;

    float oacc[16][4];
    #pragma unroll
    for (int nb = 0; nb < 16; nb++)
        #pragma unroll
        for (int i = 0; i < 4; i++) oacc[nb][i] = 0.0f;

    #pragma unroll 1
    for (int kc = 0; kc < 2; kc++) {
        #pragma unroll
        for (int i = 0; i < 4; i++) {           // O chunk [128 x 64]
            int lin = tid + i * 256;
            int r = lin >> 3, c = lin & 7;
            uint32_t off = (uint32_t)(r * 128 + ((c ^ (r & 7)) << 4));
            size_t g = (size_t)(row0 + r) * ADIM + kc * 64 + c * 8;
            cp16(sb + OUT2_AH + off, g_Oh + g);
            cp16(sb + OUT2_AL + off, g_Ol + g);
        }
        #pragma unroll
        for (int i = 0; i < 4; i++) {           // Wo chunk [64 x 128]
            int lin = tid + i * 256;
            int r = lin >> 4, c = lin & 15;
            uint32_t off = (uint32_t)(r * 256 + ((c ^ (r & 7)) << 4));
            size_t g = (size_t)(kc * 64 + r) * CIN + col0 + c * 8;
            cp16(sb + OUT2_WH + off, g_Woh + g);
            cp16(sb + OUT2_WL + off, g_Wol + g);
        }
        cp_commit(); cp_wait0();
        __syncthreads();
        #pragma unroll
        for (int ks = 0; ks < 4; ks++) {
            uint32_t ah[4], al[4];
            uint32_t ach = (uint32_t)(((2 * ks + ca) ^ swa) << 4);
            ldsm4(ah, sb + OUT2_AH + rowa * 128 + ach);
            ldsm4(al, sb + OUT2_AL + rowa * 128 + ach);
            #pragma unroll
            for (int jp = 0; jp < 8; jp++) {
                uint32_t bh[4], bl[4];
                uint32_t boff = (uint32_t)((16 * ks + rowv) * 256 + (((2 * jp + cv) ^ swv) << 4));
                ldsm4t(bh, sb + OUT2_WH + boff);
                ldsm4t(bl, sb + OUT2_WL + boff);
                mma_bf16(oacc[2 * jp],     ah, bh); mma_bf16(oacc[2 * jp + 1], ah, bh + 2);
                mma_bf16(oacc[2 * jp],     ah, bl); mma_bf16(oacc[2 * jp + 1], ah, bl + 2);
                mma_bf16(oacc[2 * jp],     al, bh); mma_bf16(oacc[2 * jp + 1], al, bh + 2);
            }
        }
        __syncthreads();
    }

    const int r0 = row0 + 16 * w + (lane >> 2);
    const int cb2 = 2 * (lane & 3);
    #pragma unroll
    for (int nb = 0; nb < 16; nb++) {
        int c = col0 + nb * 8 + cb2;
        float g0 = tanhf(fmaxf(1.0f + wgm[c], 0.0f));
        float g1 = tanhf(fmaxf(1.0f + wgm[c + 1], 0.0f));
        *(float2*)&Y[(size_t)r0 * CIN + c] =
            make_float2(oacc[nb][0] * g0, oacc[nb][1] * g1);
        *(float2*)&Y[(size_t)(r0 + 8) * CIN + c] =
            make_float2(oacc[nb][2] * g0, oacc[nb][3] * g1);
    }
}

// =====================================================================
extern "C" void kernel_launch(void* const* d_in, const int* in_sizes, int n_in,
                              void* d_out, int out_size) {
    const float* x  = (const float*)d_in[0];
    const float* Wq = (const float*)d_in[1];
    const float* Wk = (const float*)d_in[2];
    const float* Wv = (const float*)d_in[3];
    const float* Wo = (const float*)d_in[4];
    const float* wg = (const float*)d_in[5];
    float* y = (float*)d_out;

    static bool attrs_set = []() {
        cudaFuncSetAttribute(qkv2_kernel, cudaFuncAttributeMaxDynamicSharedMemorySize, QKV2_SMEM);
        cudaFuncSetAttribute(attn_kernel, cudaFuncAttributeMaxDynamicSharedMemorySize, ATTN_SMEM);
        cudaFuncSetAttribute(out2_kernel, cudaFuncAttributeMaxDynamicSharedMemorySize, OUT2_SMEM);
        return true;
    }();
    (void)attrs_set;

    convx_kernel<<<4096, 256>>>(x);
    convw_kernel<<<128, 256>>>(Wq, Wk, Wv, Wo);
    qkv2_kernel<<<dim3(128, 3), 256, QKV2_SMEM>>>();
    attn_kernel<<<dim3(NTOK / 128, BATCH), 256, ATTN_SMEM>>>();
    out2_kernel<<<dim3(128, 2), 256, OUT2_SMEM>>>(wg, y);
}